// round 3
// baseline (speedup 1.0000x reference)
#include <cuda_runtime.h>

#define TOKENS 4096
#define DIMSZ  1024
#define NSEQ   2048
#define HEADS  16
#define DHEAD  64
#define QKV_N  3072

// Scratch (device globals per harness rules; ~80MB total)
__device__ float g_xn [TOKENS * DIMSZ];
__device__ float g_qkv[TOKENS * QKV_N];
__device__ float g_att[TOKENS * DIMSZ];

// ---------------------------------------------------------------------------
// RMSNorm: xn = x / max(||x||_2, 1e-12) * sqrt(DIM) * gamma
// One block per token row; 256 threads * float4 = 1024 elems.
// ---------------------------------------------------------------------------
__global__ void __launch_bounds__(256) rmsnorm_kernel(const float* __restrict__ x,
                                                      const float* __restrict__ gamma) {
    int row = blockIdx.x;
    int tid = threadIdx.x;
    const float4 v = ((const float4*)(x + (size_t)row * DIMSZ))[tid];
    float ss = v.x * v.x + v.y * v.y + v.z * v.z + v.w * v.w;
#pragma unroll
    for (int off = 16; off >= 1; off >>= 1)
        ss += __shfl_xor_sync(0xffffffffu, ss, off);
    __shared__ float red[8];
    int lane = tid & 31, wid = tid >> 5;
    if (lane == 0) red[wid] = ss;
    __syncthreads();
    if (wid == 0) {
        float t = (lane < 8) ? red[lane] : 0.0f;
#pragma unroll
        for (int off = 4; off >= 1; off >>= 1)
            t += __shfl_xor_sync(0xffffffffu, t, off);
        if (lane == 0) red[0] = t;
    }
    __syncthreads();
    float norm = fmaxf(sqrtf(red[0]), 1e-12f);
    float scl = 32.0f / norm;  // sqrt(1024)
    const float4 g = ((const float4*)gamma)[tid];
    float4 o;
    o.x = v.x * scl * g.x;
    o.y = v.y * scl * g.y;
    o.z = v.z * scl * g.z;
    o.w = v.w * scl * g.w;
    ((float4*)(g_xn + (size_t)row * DIMSZ))[tid] = o;
}

// ---------------------------------------------------------------------------
// SGEMM: C[M,N] = A[M,1024] @ B[1024,N], all row-major. M=4096, N in {3072,1024}.
// 128x128 block tile, 8x8 per thread, K-slab 16, A stored transposed in smem.
// ---------------------------------------------------------------------------
__global__ void __launch_bounds__(256) sgemm_kernel(const float* __restrict__ A,
                                                    const float* __restrict__ B,
                                                    float* __restrict__ C, int N) {
    const int K = DIMSZ;
    __shared__ float As[16][128];
    __shared__ float Bs[16][128];
    int tid = threadIdx.x;
    int tx = tid & 15, ty = tid >> 4;
    int bm = blockIdx.y * 128, bn = blockIdx.x * 128;

    float c[8][8];
#pragma unroll
    for (int i = 0; i < 8; i++)
#pragma unroll
        for (int j = 0; j < 8; j++) c[i][j] = 0.0f;

    for (int k0 = 0; k0 < K; k0 += 16) {
#pragma unroll
        for (int t = 0; t < 2; t++) {
            int idx = tid + t * 256;
            int ra = idx >> 2, ka = (idx & 3) << 2;
            float4 av = *(const float4*)&A[(size_t)(bm + ra) * K + k0 + ka];
            As[ka + 0][ra] = av.x;
            As[ka + 1][ra] = av.y;
            As[ka + 2][ra] = av.z;
            As[ka + 3][ra] = av.w;
            int rb = idx >> 5, cb = (idx & 31) << 2;
            *(float4*)&Bs[rb][cb] = *(const float4*)&B[(size_t)(k0 + rb) * N + bn + cb];
        }
        __syncthreads();
#pragma unroll
        for (int k = 0; k < 16; k++) {
            float a[8], b[8];
            *(float4*)&a[0] = *(float4*)&As[k][ty * 4];
            *(float4*)&a[4] = *(float4*)&As[k][64 + ty * 4];
            *(float4*)&b[0] = *(float4*)&Bs[k][tx * 4];
            *(float4*)&b[4] = *(float4*)&Bs[k][64 + tx * 4];
#pragma unroll
            for (int i = 0; i < 8; i++)
#pragma unroll
                for (int j = 0; j < 8; j++)
                    c[i][j] += a[i] * b[j];
        }
        __syncthreads();
    }
#pragma unroll
    for (int i = 0; i < 8; i++) {
        int row = bm + ((i < 4) ? (ty * 4 + i) : (64 + ty * 4 + (i - 4)));
        float4 w0 = make_float4(c[i][0], c[i][1], c[i][2], c[i][3]);
        float4 w1 = make_float4(c[i][4], c[i][5], c[i][6], c[i][7]);
        *(float4*)&C[(size_t)row * N + bn + tx * 4]      = w0;
        *(float4*)&C[(size_t)row * N + bn + 64 + tx * 4] = w1;
    }
}

// ---------------------------------------------------------------------------
// Causal flash attention, fp32. Br = Bc = 64, dh = 64.
// Reads g_qkv rows: [Q(h*64) | K(1024+h*64) | V(2048+h*64)], writes g_att[t, h*64+d].
// Smem: Qt[d][qrow], KPt[d][kvrow] (reused as Pt[kv][qrow]), Vs[kv][d] = 48KB.
// Thread (tx,ty) in 16x16 owns S/P rows 4ty..4ty+3 x cols 4tx..4tx+3,
// and O rows 4ty..4ty+3 x dims 4tx..4tx+3. Row reductions via 16-lane shfl.
// ---------------------------------------------------------------------------
__global__ void __launch_bounds__(256) attn_kernel() {
    __shared__ float Qt [64 * 64];
    __shared__ float KPt[64 * 64];
    __shared__ float Vs [64 * 64];

    int tid = threadIdx.x;
    int tx = tid & 15, ty = tid >> 4;
    int qb = blockIdx.x;                 // query block 0..31
    int bh = blockIdx.y;                 // 0..31
    int b = bh >> 4, h = bh & 15;
    int t0 = b * NSEQ;

    // Load Q tile transposed: Qt[d*64 + qrow]
#pragma unroll
    for (int it = 0; it < 4; it++) {
        int idx = tid + it * 256;
        int r = idx >> 4, c4 = (idx & 15) << 2;
        float4 v = *(const float4*)&g_qkv[(size_t)(t0 + qb * 64 + r) * QKV_N + h * 64 + c4];
        Qt[(c4 + 0) * 64 + r] = v.x;
        Qt[(c4 + 1) * 64 + r] = v.y;
        Qt[(c4 + 2) * 64 + r] = v.z;
        Qt[(c4 + 3) * 64 + r] = v.w;
    }

    float o[4][4];
#pragma unroll
    for (int i = 0; i < 4; i++)
#pragma unroll
        for (int j = 0; j < 4; j++) o[i][j] = 0.0f;
    float m_[4] = {-1e30f, -1e30f, -1e30f, -1e30f};
    float l_[4] = {0.0f, 0.0f, 0.0f, 0.0f};

    for (int kb = 0; kb <= qb; kb++) {
        __syncthreads();  // prior-iter readers of KPt/Vs done (also covers Qt writes on iter 0)
        // Load K transposed + V row-major
#pragma unroll
        for (int it = 0; it < 4; it++) {
            int idx = tid + it * 256;
            int r = idx >> 4, c4 = (idx & 15) << 2;
            const float* src = &g_qkv[(size_t)(t0 + kb * 64 + r) * QKV_N + DIMSZ + h * 64 + c4];
            float4 kv = *(const float4*)src;
            KPt[(c4 + 0) * 64 + r] = kv.x;
            KPt[(c4 + 1) * 64 + r] = kv.y;
            KPt[(c4 + 2) * 64 + r] = kv.z;
            KPt[(c4 + 3) * 64 + r] = kv.w;
            *(float4*)&Vs[r * 64 + c4] = *(const float4*)(src + DIMSZ);
        }
        __syncthreads();

        // S = Q K^T for this tile
        float s[4][4];
#pragma unroll
        for (int i = 0; i < 4; i++)
#pragma unroll
            for (int j = 0; j < 4; j++) s[i][j] = 0.0f;
#pragma unroll 8
        for (int d = 0; d < 64; d++) {
            float4 q  = *(float4*)&Qt [d * 64 + ty * 4];
            float4 kk = *(float4*)&KPt[d * 64 + tx * 4];
            s[0][0] += q.x * kk.x; s[0][1] += q.x * kk.y; s[0][2] += q.x * kk.z; s[0][3] += q.x * kk.w;
            s[1][0] += q.y * kk.x; s[1][1] += q.y * kk.y; s[1][2] += q.y * kk.z; s[1][3] += q.y * kk.w;
            s[2][0] += q.z * kk.x; s[2][1] += q.z * kk.y; s[2][2] += q.z * kk.z; s[2][3] += q.z * kk.w;
            s[3][0] += q.w * kk.x; s[3][1] += q.w * kk.y; s[3][2] += q.w * kk.z; s[3][3] += q.w * kk.w;
        }
        // scale + causal mask (diagonal block only)
        const float scale = 0.125f;  // 64^-0.5
        if (kb == qb) {
#pragma unroll
            for (int i = 0; i < 4; i++)
#pragma unroll
                for (int j = 0; j < 4; j++)
                    s[i][j] = (tx * 4 + j > ty * 4 + i) ? -1e30f : s[i][j] * scale;
        } else {
#pragma unroll
            for (int i = 0; i < 4; i++)
#pragma unroll
                for (int j = 0; j < 4; j++) s[i][j] *= scale;
        }

        // Online softmax update
#pragma unroll
        for (int i = 0; i < 4; i++) {
            float tm = fmaxf(fmaxf(s[i][0], s[i][1]), fmaxf(s[i][2], s[i][3]));
            tm = fmaxf(tm, __shfl_xor_sync(0xffffffffu, tm, 8));
            tm = fmaxf(tm, __shfl_xor_sync(0xffffffffu, tm, 4));
            tm = fmaxf(tm, __shfl_xor_sync(0xffffffffu, tm, 2));
            tm = fmaxf(tm, __shfl_xor_sync(0xffffffffu, tm, 1));
            float mn = fmaxf(m_[i], tm);
            float al = __expf(m_[i] - mn);
            m_[i] = mn;
            float sum = 0.0f;
#pragma unroll
            for (int j = 0; j < 4; j++) {
                s[i][j] = __expf(s[i][j] - mn);
                sum += s[i][j];
            }
            sum += __shfl_xor_sync(0xffffffffu, sum, 8);
            sum += __shfl_xor_sync(0xffffffffu, sum, 4);
            sum += __shfl_xor_sync(0xffffffffu, sum, 2);
            sum += __shfl_xor_sync(0xffffffffu, sum, 1);
            l_[i] = l_[i] * al + sum;
#pragma unroll
            for (int cc = 0; cc < 4; cc++) o[i][cc] *= al;
        }

        __syncthreads();  // all warps done reading K from KPt
        // Write P transposed: Pt[kvcol][qrow] into KPt region
#pragma unroll
        for (int j = 0; j < 4; j++) {
            float4 w = make_float4(s[0][j], s[1][j], s[2][j], s[3][j]);
            *(float4*)&KPt[(tx * 4 + j) * 64 + ty * 4] = w;
        }
        __syncthreads();

        // O += P V
#pragma unroll 8
        for (int j = 0; j < 64; j++) {
            float4 p4 = *(float4*)&KPt[j * 64 + ty * 4];
            float4 v4 = *(float4*)&Vs [j * 64 + tx * 4];
            o[0][0] += p4.x * v4.x; o[0][1] += p4.x * v4.y; o[0][2] += p4.x * v4.z; o[0][3] += p4.x * v4.w;
            o[1][0] += p4.y * v4.x; o[1][1] += p4.y * v4.y; o[1][2] += p4.y * v4.z; o[1][3] += p4.y * v4.w;
            o[2][0] += p4.z * v4.x; o[2][1] += p4.z * v4.y; o[2][2] += p4.z * v4.z; o[2][3] += p4.z * v4.w;
            o[3][0] += p4.w * v4.x; o[3][1] += p4.w * v4.y; o[3][2] += p4.w * v4.z; o[3][3] += p4.w * v4.w;
        }
    }

    // Final normalize + write to g_att[t, h*64 + d]
#pragma unroll
    for (int i = 0; i < 4; i++) {
        float inv = 1.0f / l_[i];
        int tok = t0 + qb * 64 + ty * 4 + i;
        float4 w = make_float4(o[i][0] * inv, o[i][1] * inv, o[i][2] * inv, o[i][3] * inv);
        *(float4*)&g_att[(size_t)tok * DIMSZ + h * 64 + tx * 4] = w;
    }
}

// ---------------------------------------------------------------------------
extern "C" void kernel_launch(void* const* d_in, const int* in_sizes, int n_in,
                              void* d_out, int out_size) {
    const float* x      = (const float*)d_in[0];
    const float* gamma  = (const float*)d_in[1];
    const float* w_qkv  = (const float*)d_in[2];
    const float* w_out  = (const float*)d_in[3];
    float*       out    = (float*)d_out;
    (void)in_sizes; (void)n_in; (void)out_size;

    float *p_xn, *p_qkv, *p_att;
    cudaGetSymbolAddress((void**)&p_xn,  g_xn);
    cudaGetSymbolAddress((void**)&p_qkv, g_qkv);
    cudaGetSymbolAddress((void**)&p_att, g_att);

    rmsnorm_kernel<<<TOKENS, 256>>>(x, gamma);
    sgemm_kernel<<<dim3(QKV_N / 128, TOKENS / 128), 256>>>(p_xn, w_qkv, p_qkv, QKV_N);
    attn_kernel<<<dim3(NSEQ / 64, 2 * HEADS), 256>>>();
    sgemm_kernel<<<dim3(DIMSZ / 128, TOKENS / 128), 256>>>(p_att, w_out, out, DIMSZ);
}